// round 1
// baseline (speedup 1.0000x reference)
#include <cuda_runtime.h>
#include <cuda_bf16.h>
#include <stdint.h>

// Problem dims
#define BDIM 32
#define TDIM 512
#define IDIM 512
#define HDIM 1024
#define MDIM (TDIM * BDIM)   // 16384 rows (m = t*B + b)

// ---------------- scratch (static device globals; no allocation) ----------------
__device__ float g_xT[(size_t)MDIM * IDIM];   // x transposed to [t,b,i] rows
__device__ float g_xw[(size_t)MDIM * HDIM];   // xw0, later reused as xw1
__device__ float g_h1[(size_t)MDIM * HDIM];   // layer-0 hidden states [t,b,h]

__device__ unsigned g_bar_count = 0;
__device__ unsigned g_bar_gen   = 0;

// ---------------- transpose x[B,T,I] -> xT[(t*B+b), I] ----------------
__global__ __launch_bounds__(128) void transpose_x(const float* __restrict__ x) {
    int m = blockIdx.x;            // 0..MDIM-1
    int t = m >> 5;                // m / 32
    int b = m & 31;
    const float4* src = (const float4*)(x + ((size_t)b * TDIM + t) * IDIM);
    float4* dst = (float4*)(g_xT + (size_t)m * IDIM);
    dst[threadIdx.x] = src[threadIdx.x];   // 128 threads * float4 = 512 floats
}

// ---------------- SGEMM: C[M,1024] = A[M,K] @ W[1024,K]^T + (b1+b2) ----------------
// 128x128 tile, BK=8, 256 threads, 8x8 per thread.
#define GBK 8
#define SAP 132   // padded smem stride

__global__ __launch_bounds__(256) void gemm_bias(
    const float* __restrict__ A, const float* __restrict__ W,
    const float* __restrict__ b1, const float* __restrict__ b2,
    float* __restrict__ C, int K)
{
    __shared__ float As[GBK * SAP];
    __shared__ float Bs[GBK * SAP];

    int tid  = threadIdx.x;
    int tx   = tid & 15;          // 0..15 -> N
    int ty   = tid >> 4;          // 0..15 -> M
    int brow = blockIdx.y * 128;  // M offset
    int bcol = blockIdx.x * 128;  // N offset

    int lr = tid >> 1;            // 0..127 loader row
    int lk = (tid & 1) * 4;       // 0 or 4

    const float* Aptr = A + (size_t)(brow + lr) * K + lk;
    const float* Wptr = W + (size_t)(bcol + lr) * K + lk;

    float acc[8][8];
    #pragma unroll
    for (int i = 0; i < 8; i++)
        #pragma unroll
        for (int j = 0; j < 8; j++) acc[i][j] = 0.0f;

    for (int k0 = 0; k0 < K; k0 += GBK) {
        float4 av = *(const float4*)(Aptr + k0);
        float4 wv = *(const float4*)(Wptr + k0);
        As[(lk + 0) * SAP + lr] = av.x;
        As[(lk + 1) * SAP + lr] = av.y;
        As[(lk + 2) * SAP + lr] = av.z;
        As[(lk + 3) * SAP + lr] = av.w;
        Bs[(lk + 0) * SAP + lr] = wv.x;
        Bs[(lk + 1) * SAP + lr] = wv.y;
        Bs[(lk + 2) * SAP + lr] = wv.z;
        Bs[(lk + 3) * SAP + lr] = wv.w;
        __syncthreads();

        #pragma unroll
        for (int kk = 0; kk < GBK; kk++) {
            float a[8], bb[8];
            *(float4*)(a)     = *(const float4*)&As[kk * SAP + ty * 8];
            *(float4*)(a + 4) = *(const float4*)&As[kk * SAP + ty * 8 + 4];
            *(float4*)(bb)     = *(const float4*)&Bs[kk * SAP + tx * 8];
            *(float4*)(bb + 4) = *(const float4*)&Bs[kk * SAP + tx * 8 + 4];
            #pragma unroll
            for (int i = 0; i < 8; i++)
                #pragma unroll
                for (int j = 0; j < 8; j++)
                    acc[i][j] = fmaf(a[i], bb[j], acc[i][j]);
        }
        __syncthreads();
    }

    // bias per output column
    float bs[8];
    #pragma unroll
    for (int j = 0; j < 8; j++) {
        int col = bcol + tx * 8 + j;
        bs[j] = __ldg(b1 + col) + __ldg(b2 + col);
    }

    #pragma unroll
    for (int i = 0; i < 8; i++) {
        int row = brow + ty * 8 + i;
        float* cp = C + (size_t)row * HDIM + bcol + tx * 8;
        float4 o0, o1;
        o0.x = acc[i][0] + bs[0]; o0.y = acc[i][1] + bs[1];
        o0.z = acc[i][2] + bs[2]; o0.w = acc[i][3] + bs[3];
        o1.x = acc[i][4] + bs[4]; o1.y = acc[i][5] + bs[5];
        o1.z = acc[i][6] + bs[6]; o1.w = acc[i][7] + bs[7];
        *(float4*)(cp)     = o0;
        *(float4*)(cp + 4) = o1;
    }
}

// ---------------- persistent recurrence ----------------
// 128 CTAs x 256 threads; CTA cb owns output columns [cb*8, cb*8+8).
// Whh slice (8x1024) lives in smem for the whole kernel; h (32x1024) staged
// to smem each step via __ldcg (L2-fresh). Grid-wide sense-reversal barrier
// per timestep.
#define RSTR 1028                 // padded float stride (conflict-free)
#define NBLK 128
#define RECUR_SMEM_FLOATS ((8 + 32) * RSTR)
#define RECUR_SMEM_BYTES (RECUR_SMEM_FLOATS * 4)

extern __shared__ float s_recur[];

__global__ __launch_bounds__(256) void recur(
    const float* __restrict__ xw,   // [t*B+b, H] precomputed input projection (+biases)
    const float* __restrict__ Whh,  // [H, H]
    float* __restrict__ hio,        // layer0: g_h1 [t,b,h] ; layer1: d_out [b,t,h]
    int bth)                        // 0 -> [T,B,H] layout, 1 -> [B,T,H]
{
    float* Ws = s_recur;              // 8 * RSTR
    float* hs = s_recur + 8 * RSTR;   // 32 * RSTR

    int tid = threadIdx.x;
    int cb  = blockIdx.x;             // 0..127
    int j   = tid & 7;
    int b   = tid >> 3;               // 0..31
    int col = cb * 8 + j;

    // load this CTA's weight slice into smem (row j of slice = Whh[col_j, :])
    for (int idx = tid; idx < 8 * 256; idx += 256) {
        int jj = idx >> 8;
        int kq = idx & 255;
        float4 w = *(const float4*)(Whh + (size_t)(cb * 8 + jj) * HDIM + kq * 4);
        *(float4*)&Ws[jj * RSTR + kq * 4] = w;
    }

    const float4* wp = (const float4*)&Ws[j * RSTR];
    const float4* hp = (const float4*)&hs[b * RSTR];

    for (int t = 0; t < TDIM; t++) {
        // stage h_{t-1} into smem (zeros at t=0)
        if (t == 0) {
            float4 z = make_float4(0.f, 0.f, 0.f, 0.f);
            for (int idx = tid; idx < 32 * 256; idx += 256) {
                int bb = idx >> 8, kq = idx & 255;
                *(float4*)&hs[bb * RSTR + kq * 4] = z;
            }
        } else {
            for (int idx = tid; idx < 32 * 256; idx += 256) {
                int bb = idx >> 8, kq = idx & 255;
                const float* src = bth
                    ? hio + ((size_t)bb * TDIM + (t - 1)) * HDIM + kq * 4
                    : hio + ((size_t)(t - 1) * BDIM + bb) * HDIM + kq * 4;
                *(float4*)&hs[bb * RSTR + kq * 4] = __ldcg((const float4*)src);
            }
        }
        __syncthreads();

        float acc = __ldg(xw + ((size_t)t * BDIM + b) * HDIM + col);
        #pragma unroll 16
        for (int kq = 0; kq < 256; kq++) {
            float4 w = wp[kq];
            float4 h = hp[kq];
            acc = fmaf(h.x, w.x, acc);
            acc = fmaf(h.y, w.y, acc);
            acc = fmaf(h.z, w.z, acc);
            acc = fmaf(h.w, w.w, acc);
        }
        float hv = tanhf(acc);

        float* dst = bth ? hio + ((size_t)b * TDIM + t) * HDIM + col
                         : hio + ((size_t)t * BDIM + b) * HDIM + col;
        *dst = hv;

        __threadfence();     // make my store visible (gpu scope) before arriving
        __syncthreads();     // all threads in CTA done writing

        // grid-wide barrier (sense-reversal; all NBLK CTAs are resident)
        if (tid == 0) {
            unsigned g = *((volatile unsigned*)&g_bar_gen);
            if (atomicAdd(&g_bar_count, 1u) == NBLK - 1) {
                atomicExch(&g_bar_count, 0u);
                __threadfence();
                atomicExch(&g_bar_gen, g + 1u);
            } else {
                unsigned cur;
                do {
                    asm volatile("ld.acquire.gpu.u32 %0, [%1];"
                                 : "=r"(cur) : "l"(&g_bar_gen));
                    if (cur != g) break;
                    __nanosleep(64);
                } while (true);
            }
        }
        __syncthreads();
    }
}

// ---------------- launch ----------------
extern "C" void kernel_launch(void* const* d_in, const int* in_sizes, int n_in,
                              void* d_out, int out_size)
{
    const float* x    = (const float*)d_in[0];
    const float* Wih0 = (const float*)d_in[1];
    const float* Whh0 = (const float*)d_in[2];
    const float* bih0 = (const float*)d_in[3];
    const float* bhh0 = (const float*)d_in[4];
    const float* Wih1 = (const float*)d_in[5];
    const float* Whh1 = (const float*)d_in[6];
    const float* bih1 = (const float*)d_in[7];
    const float* bhh1 = (const float*)d_in[8];
    float* out = (float*)d_out;

    float *xT, *xw, *h1;
    cudaGetSymbolAddress((void**)&xT, g_xT);
    cudaGetSymbolAddress((void**)&xw, g_xw);
    cudaGetSymbolAddress((void**)&h1, g_h1);

    cudaFuncSetAttribute(recur, cudaFuncAttributeMaxDynamicSharedMemorySize,
                         RECUR_SMEM_BYTES);

    // 1) transpose x -> xT[(t*B+b), I]
    transpose_x<<<MDIM, 128>>>(x);

    // 2) xw0 = xT @ Wih0^T + (bih0 + bhh0)
    gemm_bias<<<dim3(HDIM / 128, MDIM / 128), 256>>>(xT, Wih0, bih0, bhh0, xw, IDIM);

    // 3) layer-0 recurrence -> h1 [t,b,h]
    recur<<<NBLK, 256, RECUR_SMEM_BYTES>>>(xw, Whh0, h1, 0);

    // 4) xw1 = h1 @ Wih1^T + (bih1 + bhh1)   (reuses xw scratch)
    gemm_bias<<<dim3(HDIM / 128, MDIM / 128), 256>>>(h1, Wih1, bih1, bhh1, xw, HDIM);

    // 5) layer-1 recurrence -> d_out [b,t,h]
    recur<<<NBLK, 256, RECUR_SMEM_BYTES>>>(xw, Whh1, out, 1);
}

// round 2
// speedup vs baseline: 1.1781x; 1.1781x over previous
#include <cuda_runtime.h>
#include <cuda_bf16.h>
#include <stdint.h>

// Problem dims
#define BDIM 32
#define TDIM 512
#define IDIM 512
#define HDIM 1024
#define MDIM (TDIM * BDIM)   // 16384 rows (m = t*B + b)

// ---------------- scratch (static device globals; no allocation) ----------------
__device__ float g_xT[(size_t)MDIM * IDIM];   // x transposed to [t,b,i] rows
__device__ float g_xw[(size_t)MDIM * HDIM];   // xw0, later reused as xw1
__device__ float g_h1[(size_t)MDIM * HDIM];   // layer-0 hidden states [t,b,h]

__device__ unsigned g_bar_count = 0;
__device__ unsigned g_bar_gen   = 0;

// ---------------- f32x2 / cp.async helpers ----------------
__device__ __forceinline__ void ffma2(unsigned long long& d,
                                      unsigned long long a,
                                      unsigned long long b) {
    asm("fma.rn.f32x2 %0, %1, %2, %0;" : "+l"(d) : "l"(a), "l"(b));
}
__device__ __forceinline__ unsigned long long splat2(float x) {
    unsigned long long r;
    asm("mov.b64 %0, {%1, %1};" : "=l"(r) : "f"(x));
    return r;
}
__device__ __forceinline__ float2 unpack2(unsigned long long v) {
    float lo, hi;
    asm("mov.b64 {%0, %1}, %2;" : "=f"(lo), "=f"(hi) : "l"(v));
    return make_float2(lo, hi);
}
__device__ __forceinline__ void cp_async16(uint32_t saddr, const void* g) {
    asm volatile("cp.async.cg.shared.global [%0], [%1], 16;" :: "r"(saddr), "l"(g));
}
__device__ __forceinline__ void cp_commit() {
    asm volatile("cp.async.commit_group;");
}
template <int N>
__device__ __forceinline__ void cp_wait() {
    asm volatile("cp.async.wait_group %0;" :: "n"(N));
}

// ---------------- transpose x[B,T,I] -> xT[(t*B+b), I] ----------------
__global__ __launch_bounds__(128) void transpose_x(const float* __restrict__ x) {
    int m = blockIdx.x;            // 0..MDIM-1
    int t = m >> 5;                // m / 32
    int b = m & 31;
    const float4* src = (const float4*)(x + ((size_t)b * TDIM + t) * IDIM);
    float4* dst = (float4*)(g_xT + (size_t)m * IDIM);
    dst[threadIdx.x] = src[threadIdx.x];   // 128 threads * float4 = 512 floats
}

// ---------------- SGEMM: C[M,1024] = A[M,K] @ W[1024,K]^T + (b1+b2) ----------------
// 128x128 tile, BK=8, 256 threads, 8x8 per thread, FFMA2 inner loop.
#define GBK 8
#define SAP 132   // padded smem stride (528B, 16B-aligned rows)

__global__ __launch_bounds__(256) void gemm_bias(
    const float* __restrict__ A, const float* __restrict__ W,
    const float* __restrict__ b1, const float* __restrict__ b2,
    float* __restrict__ C, int K)
{
    __shared__ float As[GBK * SAP];
    __shared__ float Bs[GBK * SAP];

    int tid  = threadIdx.x;
    int tx   = tid & 15;          // 0..15 -> N
    int ty   = tid >> 4;          // 0..15 -> M
    int brow = blockIdx.y * 128;  // M offset
    int bcol = blockIdx.x * 128;  // N offset

    int lr = tid >> 1;            // 0..127 loader row
    int lk = (tid & 1) * 4;       // 0 or 4

    const float* Aptr = A + (size_t)(brow + lr) * K + lk;
    const float* Wptr = W + (size_t)(bcol + lr) * K + lk;

    // acc pairs: accp[p][j] holds rows (2p, 2p+1) of the 8x8 tile, column j
    unsigned long long accp[4][8];
    #pragma unroll
    for (int p = 0; p < 4; p++)
        #pragma unroll
        for (int j = 0; j < 8; j++) accp[p][j] = 0ull;

    for (int k0 = 0; k0 < K; k0 += GBK) {
        float4 av = *(const float4*)(Aptr + k0);
        float4 wv = *(const float4*)(Wptr + k0);
        As[(lk + 0) * SAP + lr] = av.x;
        As[(lk + 1) * SAP + lr] = av.y;
        As[(lk + 2) * SAP + lr] = av.z;
        As[(lk + 3) * SAP + lr] = av.w;
        Bs[(lk + 0) * SAP + lr] = wv.x;
        Bs[(lk + 1) * SAP + lr] = wv.y;
        Bs[(lk + 2) * SAP + lr] = wv.z;
        Bs[(lk + 3) * SAP + lr] = wv.w;
        __syncthreads();

        #pragma unroll
        for (int kk = 0; kk < GBK; kk++) {
            const float* abase = &As[kk * SAP + ty * 8];
            ulonglong2 a01 = *(const ulonglong2*)abase;        // rows (0,1),(2,3)
            ulonglong2 a23 = *(const ulonglong2*)(abase + 4);  // rows (4,5),(6,7)
            unsigned long long ap[4] = {a01.x, a01.y, a23.x, a23.y};

            const float* bbase = &Bs[kk * SAP + tx * 8];
            float4 bv0 = *(const float4*)bbase;
            float4 bv1 = *(const float4*)(bbase + 4);
            unsigned long long bsp[8] = {
                splat2(bv0.x), splat2(bv0.y), splat2(bv0.z), splat2(bv0.w),
                splat2(bv1.x), splat2(bv1.y), splat2(bv1.z), splat2(bv1.w)};

            #pragma unroll
            for (int p = 0; p < 4; p++)
                #pragma unroll
                for (int j = 0; j < 8; j++)
                    ffma2(accp[p][j], ap[p], bsp[j]);
        }
        __syncthreads();
    }

    // bias per output column
    float bs[8];
    #pragma unroll
    for (int j = 0; j < 8; j++) {
        int col = bcol + tx * 8 + j;
        bs[j] = __ldg(b1 + col) + __ldg(b2 + col);
    }

    #pragma unroll
    for (int p = 0; p < 4; p++) {
        float2 u[8];
        #pragma unroll
        for (int j = 0; j < 8; j++) u[j] = unpack2(accp[p][j]);

        int row0 = brow + ty * 8 + 2 * p;
        float* cp0 = C + (size_t)row0 * HDIM + bcol + tx * 8;
        float* cp1 = cp0 + HDIM;
        float4 o;
        o.x = u[0].x + bs[0]; o.y = u[1].x + bs[1];
        o.z = u[2].x + bs[2]; o.w = u[3].x + bs[3];
        *(float4*)(cp0) = o;
        o.x = u[4].x + bs[4]; o.y = u[5].x + bs[5];
        o.z = u[6].x + bs[6]; o.w = u[7].x + bs[7];
        *(float4*)(cp0 + 4) = o;
        o.x = u[0].y + bs[0]; o.y = u[1].y + bs[1];
        o.z = u[2].y + bs[2]; o.w = u[3].y + bs[3];
        *(float4*)(cp1) = o;
        o.x = u[4].y + bs[4]; o.y = u[5].y + bs[5];
        o.z = u[6].y + bs[6]; o.w = u[7].y + bs[7];
        *(float4*)(cp1 + 4) = o;
    }
}

// ---------------- persistent recurrence ----------------
// 128 CTAs x 256 threads; CTA cb owns output columns [cb*8, cb*8+8).
// Whh slice (8x1024) resident in smem; h_{t-1} (32x1024) staged each step via
// cp.async in 4 K-chunks overlapped with the FFMA2 dot products.
#define RSTR 1028                 // padded float stride (4112B, 16B-aligned, conflict-free)
#define NBLK 128
#define RECUR_SMEM_FLOATS ((8 + 32) * RSTR)
#define RECUR_SMEM_BYTES (RECUR_SMEM_FLOATS * 4)

extern __shared__ float s_recur[];

__global__ __launch_bounds__(256) void recur(
    const float* __restrict__ xw,   // [t*B+b, H] input projection (+biases)
    const float* __restrict__ Whh,  // [H, H]
    float* __restrict__ hio,        // layer0: g_h1 [t,b,h] ; layer1: d_out [b,t,h]
    int bth)                        // 0 -> [T,B,H] layout, 1 -> [B,T,H]
{
    float* Ws = s_recur;              // 8 * RSTR
    float* hs = s_recur + 8 * RSTR;   // 32 * RSTR

    int tid = threadIdx.x;
    int cb  = blockIdx.x;             // 0..127
    int j   = tid & 7;
    int b   = tid >> 3;               // 0..31
    int col = cb * 8 + j;

    // staging coords: thread covers float4 column q of rows r0, r0+4, ..., r0+28
    int q  = tid & 63;                // float4 col within a 64-float4 chunk
    int r0 = tid >> 6;                // 0..3

    // load this CTA's weight slice into smem
    for (int idx = tid; idx < 8 * 256; idx += 256) {
        int jj = idx >> 8;
        int kq = idx & 255;
        float4 w = *(const float4*)(Whh + (size_t)(cb * 8 + jj) * HDIM + kq * 4);
        *(float4*)&Ws[jj * RSTR + kq * 4] = w;
    }
    // zero h staging area (valid h_{-1} = 0 for t=0)
    {
        float4 z = make_float4(0.f, 0.f, 0.f, 0.f);
        for (int idx = tid; idx < 32 * 256; idx += 256) {
            int bb = idx >> 8, kq = idx & 255;
            *(float4*)&hs[bb * RSTR + kq * 4] = z;
        }
    }

    const ulonglong2* wrow = (const ulonglong2*)&Ws[j * RSTR];
    const ulonglong2* hrow = (const ulonglong2*)&hs[b * RSTR];

    // precompute smem byte addresses for staging destinations
    uint32_t hs_base = (uint32_t)__cvta_generic_to_shared(hs);

    for (int t = 0; t < TDIM; t++) {
        // prefetch xw early (independent of h)
        float xwv = __ldg(xw + ((size_t)t * BDIM + b) * HDIM + col);

        // issue all 4 staging chunks (h_{t-1}) up front
        if (t > 0) {
            #pragma unroll
            for (int c = 0; c < 4; c++) {
                #pragma unroll
                for (int s = 0; s < 8; s++) {
                    int row = r0 + 4 * s;
                    int fq  = c * 64 + q;   // float4 column 0..255
                    const float* src = bth
                        ? hio + ((size_t)row * TDIM + (t - 1)) * HDIM + fq * 4
                        : hio + ((size_t)(t - 1) * BDIM + row) * HDIM + fq * 4;
                    uint32_t dst = hs_base + (uint32_t)(row * RSTR + fq * 4) * 4u;
                    cp_async16(dst, src);
                }
                cp_commit();
            }
        }

        unsigned long long a0 = 0ull, a1 = 0ull, a2 = 0ull, a3 = 0ull;

        #pragma unroll
        for (int c = 0; c < 4; c++) {
            if (t > 0) {
                if (c == 0) cp_wait<3>();
                else if (c == 1) cp_wait<2>();
                else if (c == 2) cp_wait<1>();
                else cp_wait<0>();
            }
            __syncthreads();   // chunk c visible to all threads

            int kqb = c * 64;
            #pragma unroll 8
            for (int u = 0; u < 64; u += 2) {
                ulonglong2 w0 = wrow[kqb + u];
                ulonglong2 h0 = hrow[kqb + u];
                ulonglong2 w1 = wrow[kqb + u + 1];
                ulonglong2 h1 = hrow[kqb + u + 1];
                ffma2(a0, h0.x, w0.x);
                ffma2(a1, h0.y, w0.y);
                ffma2(a2, h1.x, w1.x);
                ffma2(a3, h1.y, w1.y);
            }
        }

        float2 u0 = unpack2(a0), u1 = unpack2(a1);
        float2 u2 = unpack2(a2), u3 = unpack2(a3);
        float acc = xwv + ((u0.x + u0.y) + (u1.x + u1.y))
                        + ((u2.x + u2.y) + (u3.x + u3.y));
        float hv = tanhf(acc);

        float* dst = bth ? hio + ((size_t)b * TDIM + t) * HDIM + col
                         : hio + ((size_t)t * BDIM + b) * HDIM + col;
        *dst = hv;

        __syncthreads();     // all h stores of this CTA done

        // grid-wide barrier (release on arrive, acquire on spin; CG grid.sync pattern)
        if (tid == 0) {
            unsigned g;
            asm volatile("ld.relaxed.gpu.u32 %0, [%1];" : "=r"(g) : "l"(&g_bar_gen));
            unsigned old;
            asm volatile("atom.add.release.gpu.u32 %0, [%1], 1;"
                         : "=r"(old) : "l"(&g_bar_count));
            if (old == NBLK - 1) {
                asm volatile("st.relaxed.gpu.u32 [%0], %1;" :: "l"(&g_bar_count), "r"(0u));
                asm volatile("st.release.gpu.u32 [%0], %1;" :: "l"(&g_bar_gen), "r"(g + 1u));
            } else {
                unsigned cur;
                do {
                    asm volatile("ld.acquire.gpu.u32 %0, [%1];"
                                 : "=r"(cur) : "l"(&g_bar_gen));
                } while (cur == g);
            }
        }
        __syncthreads();
    }
}

// ---------------- launch ----------------
extern "C" void kernel_launch(void* const* d_in, const int* in_sizes, int n_in,
                              void* d_out, int out_size)
{
    const float* x    = (const float*)d_in[0];
    const float* Wih0 = (const float*)d_in[1];
    const float* Whh0 = (const float*)d_in[2];
    const float* bih0 = (const float*)d_in[3];
    const float* bhh0 = (const float*)d_in[4];
    const float* Wih1 = (const float*)d_in[5];
    const float* Whh1 = (const float*)d_in[6];
    const float* bih1 = (const float*)d_in[7];
    const float* bhh1 = (const float*)d_in[8];
    float* out = (float*)d_out;

    float *xT, *xw, *h1;
    cudaGetSymbolAddress((void**)&xT, g_xT);
    cudaGetSymbolAddress((void**)&xw, g_xw);
    cudaGetSymbolAddress((void**)&h1, g_h1);

    cudaFuncSetAttribute(recur, cudaFuncAttributeMaxDynamicSharedMemorySize,
                         RECUR_SMEM_BYTES);

    // 1) transpose x -> xT[(t*B+b), I]
    transpose_x<<<MDIM, 128>>>(x);

    // 2) xw0 = xT @ Wih0^T + (bih0 + bhh0)
    gemm_bias<<<dim3(HDIM / 128, MDIM / 128), 256>>>(xT, Wih0, bih0, bhh0, xw, IDIM);

    // 3) layer-0 recurrence -> h1 [t,b,h]
    recur<<<NBLK, 256, RECUR_SMEM_BYTES>>>(xw, Whh0, h1, 0);

    // 4) xw1 = h1 @ Wih1^T + (bih1 + bhh1)   (reuses xw scratch)
    gemm_bias<<<dim3(HDIM / 128, MDIM / 128), 256>>>(h1, Wih1, bih1, bhh1, xw, HDIM);

    // 5) layer-1 recurrence -> d_out [b,t,h]
    recur<<<NBLK, 256, RECUR_SMEM_BYTES>>>(xw, Whh1, out, 1);
}